// round 11
// baseline (speedup 1.0000x reference)
#include <cuda_runtime.h>
#include <cstdint>

// Problem constants
#define B_      16
#define C_      64
#define HW_     65536      // 256*256

// Radix sort: 4 stable LSD passes of 8 bits over the 32-bit ordered-float
// value (high half of a u64 key). Low bits: channel<<16 | spatial(16).
// Keys generated in spatial order; stability => jnp argsort tie order.
#define THREADS 256
#define NW      8
#define IPT     4
#define BSIZE   1024               // THREADS * IPT
#define NBLK    64                 // HW_ / BSIZE
#define GRID    (B_ * NBLK)        // 1024 scatter blocks
#define RSIZE   (B_ * 256 * NBLK)  // 262144 entries per hist region

__device__ __align__(16) unsigned long long g_kv0[B_ * HW_];
__device__ __align__(16) unsigned long long g_kv1[B_ * HW_];
// 4 rotating RAW histogram regions (never scanned; scatter fuses the scan).
// Zero-rotation: s0 zeroes R3, s1->R0, s2->R1, s3->R2. Producers:
// compute_keys->R0, s0->R1, s1->R2, s2->R3. Readers: s_p reads R_p.
__device__ __align__(16) unsigned int g_hist[4][RSIZE];

__device__ __forceinline__ unsigned int f2ord(float f) {
    unsigned int u = __float_as_uint(f);
    return (u & 0x80000000u) ? ~u : (u | 0x80000000u);
}

// -------------------------------------------------------------------------
// Kernel 1: channel max + argmax (first occurrence), emit u64 keys AND
// accumulate the pass-0 raw histogram into g_hist[0] (zero at entry;
// re-zeroed each replay by scatter pass 1). Channel axis split 4-ways
// across lanes; shfl_xor(1),(2) combine. grid = 4096 x 256.
// -------------------------------------------------------------------------
__global__ void compute_keys_kernel(const float* __restrict__ x) {
    __shared__ unsigned int h[256];
    h[threadIdx.x] = 0;
    __syncthreads();

    int gid   = blockIdx.x * 256 + threadIdx.x;   // 0 .. 1048575
    int chunk = gid & 3;                          // channel chunk (16 ch each)
    int qg    = gid >> 2;                         // global pixel-group
    int batch = qg >> 14;
    int q     = qg & 16383;

    const float4* xb = reinterpret_cast<const float4*>(x)
                       + (size_t)batch * (C_ * (HW_ / 4))
                       + (size_t)(chunk * 16) * (HW_ / 4) + q;

    float4 best = xb[0];
    int c0 = 0, c1 = 0, c2 = 0, c3 = 0;
    #pragma unroll
    for (int c = 1; c < 16; ++c) {
        float4 v = xb[(size_t)c * (HW_ / 4)];
        if (v.x > best.x) { best.x = v.x; c0 = c; }
        if (v.y > best.y) { best.y = v.y; c1 = c; }
        if (v.z > best.z) { best.z = v.z; c2 = c; }
        if (v.w > best.w) { best.w = v.w; c3 = c; }
    }
    int cb = chunk * 16;
    c0 += cb; c1 += cb; c2 += cb; c3 += cb;

    // Cross-chunk combine; equal value -> smaller channel = first occurrence.
    #pragma unroll
    for (int m = 1; m <= 2; m <<= 1) {
        float ox = __shfl_xor_sync(0xffffffffu, best.x, m);
        float oy = __shfl_xor_sync(0xffffffffu, best.y, m);
        float oz = __shfl_xor_sync(0xffffffffu, best.z, m);
        float ow = __shfl_xor_sync(0xffffffffu, best.w, m);
        int   o0 = __shfl_xor_sync(0xffffffffu, c0, m);
        int   o1 = __shfl_xor_sync(0xffffffffu, c1, m);
        int   o2 = __shfl_xor_sync(0xffffffffu, c2, m);
        int   o3 = __shfl_xor_sync(0xffffffffu, c3, m);
        if (ox > best.x || (ox == best.x && o0 < c0)) { best.x = ox; c0 = o0; }
        if (oy > best.y || (oy == best.y && o1 < c1)) { best.y = oy; c1 = o1; }
        if (oz > best.z || (oz == best.z && o2 < c2)) { best.z = oz; c2 = o2; }
        if (ow > best.w || (ow == best.w && o3 < c3)) { best.w = ow; c3 = o3; }
    }

    if (chunk == 0) {
        unsigned int e0 = f2ord(best.x), e1 = f2ord(best.y);
        unsigned int e2 = f2ord(best.z), e3 = f2ord(best.w);
        size_t o = (size_t)batch * HW_;
        unsigned int s = (unsigned int)q * 4u;
        ulonglong2 k01, k23;
        k01.x = ((unsigned long long)e0 << 32) | ((unsigned)c0 << 16) | (s + 0u);
        k01.y = ((unsigned long long)e1 << 32) | ((unsigned)c1 << 16) | (s + 1u);
        k23.x = ((unsigned long long)e2 << 32) | ((unsigned)c2 << 16) | (s + 2u);
        k23.y = ((unsigned long long)e3 << 32) | ((unsigned)c3 << 16) | (s + 3u);
        *reinterpret_cast<ulonglong2*>(g_kv0 + o + s)     = k01;
        *reinterpret_cast<ulonglong2*>(g_kv0 + o + s + 2) = k23;

        atomicAdd(&h[e0 & 255u], 1u);
        atomicAdd(&h[e1 & 255u], 1u);
        atomicAdd(&h[e2 & 255u], 1u);
        atomicAdd(&h[e3 & 255u], 1u);
    }
    __syncthreads();

    int local = (blockIdx.x & 255) >> 2;         // dest scatter block
    unsigned int cnt = h[threadIdx.x];
    if (cnt)
        atomicAdd(&g_hist[0][((size_t)batch * 256 + threadIdx.x) * NBLK + local], cnt);
}

// -------------------------------------------------------------------------
// Kernel 2: stable scatter with FUSED histogram scan. Thread tid(=bin)
// reads its bin's 64 raw per-block counts: bintot (batch bin total) and
// lpre (count in blocks < local). Block scan of bintot -> bin base.
// Streaming-ballot ranking; smem exchange for coalesced writes.
// RIN = hist region read; ROUT = region produced; RZERO = region zeroed.
// grid = 1024 x 256.
// -------------------------------------------------------------------------
template <int SHIFT, int RIN, int ROUT, int RZERO, bool LAST>
__global__ void __launch_bounds__(THREADS, 4)
scatter_kernel(float4* __restrict__ outv) {
    __shared__ unsigned int       wh[NW][256];
    __shared__ unsigned long long s_kv[BSIZE];
    __shared__ unsigned int       dstart[256];
    __shared__ unsigned int       gbase[256];
    __shared__ unsigned int       sw[NW];
    __shared__ unsigned int       sw2[NW];

    const unsigned long long* __restrict__ in_kv  = (RIN & 1) ? g_kv1 : g_kv0;
    unsigned long long*       __restrict__ out_kv = (RIN & 1) ? g_kv0 : g_kv1;

    int tid = threadIdx.x;
    int w = tid >> 5, lane = tid & 31;
    unsigned int lt = (1u << lane) - 1u;
    for (int j = tid; j < NW * 256; j += THREADS)
        (&wh[0][0])[j] = 0;

    int blk = blockIdx.x, batch = blk >> 6, local = blk & 63;

    // Zero this block's slice of the rotation region (consumed last pass).
    g_hist[RZERO][(size_t)blk * 256 + tid] = 0u;
    __syncthreads();

    size_t base = (size_t)blk * BSIZE + (size_t)w * (32 * IPT);

    unsigned long long kv[IPT];
    unsigned int d[IPT];
    unsigned int rank[IPT];

    #pragma unroll
    for (int i = 0; i < IPT; ++i) {
        kv[i] = in_kv[base + i * 32 + lane];
        d[i] = (unsigned)(kv[i] >> (32 + SHIFT)) & 255u;
        rank[i] = 0;
    }

    // Streaming-ballot ranking (per-warp, stable).
    #pragma unroll
    for (int j = 0; j < IPT; ++j) {
        unsigned int bal[8];
        #pragma unroll
        for (int b = 0; b < 8; ++b)
            bal[b] = __ballot_sync(0xffffffffu, (d[j] >> b) & 1u);
        #pragma unroll
        for (int i = j; i < IPT; ++i) {
            unsigned int m = 0xffffffffu;
            #pragma unroll
            for (int b = 0; b < 8; ++b)
                m &= bal[b] ^ (((d[i] >> b) & 1u) - 1u);
            if (i == j) {
                unsigned int rw = __popc(m & lt);
                rank[i] += rw;
                if (rw == 0)
                    atomicAdd(&wh[w][d[i]], __popc(m));
            } else {
                rank[i] += __popc(m);
            }
        }
    }

    // Fused hist scan: bin = tid. 64 raw counts of this bin across blocks.
    const uint4* hp = reinterpret_cast<const uint4*>(
        g_hist[RIN] + ((size_t)batch * 256 + tid) * NBLK);
    unsigned int lpre = 0, bintot = 0;
    #pragma unroll
    for (int j = 0; j < 16; ++j) {
        uint4 hv = hp[j];
        bintot += hv.x + hv.y + hv.z + hv.w;
        if (j * 4 + 0 < local) lpre += hv.x;
        if (j * 4 + 1 < local) lpre += hv.y;
        if (j * 4 + 2 < local) lpre += hv.z;
        if (j * 4 + 3 < local) lpre += hv.w;
    }
    __syncthreads();

    // Per-bin cross-warp scan of own-block counts (bin = tid).
    unsigned int running = 0;
    #pragma unroll
    for (int q = 0; q < NW; ++q) {
        unsigned int t = wh[q][tid];
        wh[q][tid] = running;
        running += t;
    }

    // Two block-wide exclusive scans (own counts -> dstart; bintot -> base).
    unsigned int inc1 = running, inc2 = bintot;
    #pragma unroll
    for (int o = 1; o < 32; o <<= 1) {
        unsigned int t1 = __shfl_up_sync(0xffffffffu, inc1, o);
        unsigned int t2 = __shfl_up_sync(0xffffffffu, inc2, o);
        if (lane >= o) { inc1 += t1; inc2 += t2; }
    }
    if (lane == 31) { sw[w] = inc1; sw2[w] = inc2; }
    __syncthreads();
    if (tid == 0) {
        unsigned int r1 = 0, r2 = 0;
        #pragma unroll
        for (int q = 0; q < NW; ++q) {
            unsigned int t1 = sw[q];  sw[q]  = r1; r1 += t1;
            unsigned int t2 = sw2[q]; sw2[q] = r2; r2 += t2;
        }
    }
    __syncthreads();
    unsigned int excl    = inc1 - running + sw[w];    // in-block digit start
    unsigned int binBase = inc2 - bintot  + sw2[w];   // batch-global bin start
    dstart[tid] = excl;
    gbase[tid]  = binBase + lpre - excl;
    __syncthreads();

    // Exchange into block-digit-sorted order.
    #pragma unroll
    for (int i = 0; i < IPT; ++i) {
        unsigned int p = dstart[d[i]] + wh[w][d[i]] + rank[i];
        s_kv[p] = kv[i];
    }
    __syncthreads();

    // Coalesced write-out; global pos = gbase[digit] + p.
    size_t obase = (size_t)batch * HW_;
    #pragma unroll
    for (int j = 0; j < IPT; ++j) {
        unsigned int p = (unsigned int)tid + j * THREADS;
        unsigned long long k = s_kv[p];
        unsigned int dd = (unsigned)(k >> (32 + SHIFT)) & 255u;
        unsigned int pos = gbase[dd] + p;
        if (!LAST) {
            out_kv[obase + pos] = k;
            unsigned int d2 = (unsigned)(k >> (40 + SHIFT)) & 255u;
            atomicAdd(&g_hist[ROUT][((size_t)batch * 256 + d2) * NBLK + (pos >> 10)], 1u);
        } else {
            unsigned int hi = (unsigned int)(k >> 32);
            unsigned int u  = (hi & 0x80000000u) ? (hi ^ 0x80000000u) : ~hi;
            unsigned int lo = (unsigned int)k & 0x3FFFFFu;   // c<<16 | s == flat idx
            unsigned int s  = lo & 0xFFFFu;
            float4 o;
            o.x = __uint_as_float(u);
            o.y = (float)lo;                      // c*65536 + s, < 2^22, exact
            o.z = (float)(s >> 8);                // row (W=256)
            o.w = (float)(s & 255u);              // col
            outv[obase + pos] = o;
        }
    }
}

// -------------------------------------------------------------------------
// Region rotation (verified across graph replays; globals start zeroed):
//   R0: ck produces, s0 reads, s1 zeroes.
//   R1: s0 produces, s1 reads, s2 zeroes.
//   R2: s1 produces, s2 reads, s3 zeroes.
//   R3: s2 produces, s3 reads, s0 zeroes (of the SAME replay, before s2).
// -------------------------------------------------------------------------
extern "C" void kernel_launch(void* const* d_in, const int* in_sizes, int n_in,
                              void* d_out, int out_size) {
    const float* x = (const float*)d_in[0];
    float4* out = (float4*)d_out;

    compute_keys_kernel<<<4096, 256>>>(x);                        // keys + hist -> R0
    scatter_kernel< 0, 0, 1, 3, false><<<GRID, THREADS>>>(nullptr); // kv0->kv1
    scatter_kernel< 8, 1, 2, 0, false><<<GRID, THREADS>>>(nullptr); // kv1->kv0
    scatter_kernel<16, 2, 3, 1, false><<<GRID, THREADS>>>(nullptr); // kv0->kv1
    scatter_kernel<24, 3, 0, 2, true ><<<GRID, THREADS>>>(out);     // kv1->d_out
}

// round 12
// speedup vs baseline: 1.3650x; 1.3650x over previous
#include <cuda_runtime.h>
#include <cstdint>

// Problem constants
#define B_      16
#define C_      64
#define HW_     65536      // 256*256

// Radix sort: 4 stable LSD passes of 8 bits over the 32-bit ordered-float
// value (high half of a u64 key). Low bits: channel<<16 | spatial(16).
// Keys generated in spatial order; stability => jnp argsort tie order.
#define THREADS 256
#define NW      8
#define IPT     4
#define BSIZE   1024               // THREADS * IPT
#define NBLK    64                 // HW_ / BSIZE
#define GRID    (B_ * NBLK)        // 1024 scatter blocks
#define RSIZE   (B_ * NBLK * 256)  // 262144 entries per hist region

__device__ __align__(16) unsigned long long g_kv0[B_ * HW_];
__device__ __align__(16) unsigned long long g_kv1[B_ * HW_];
// 4 rotating RAW histogram regions, layout (batch, local_block, bin) --
// bin is the fastest axis so the fused scan reads are COALESCED (1 line
// per warp-load). Zero-rotation: s0 zeroes R3, s1->R0, s2->R1, s3->R2.
// Producers: compute_keys->R0, s0->R1, s1->R2, s2->R3. Readers: s_p -> R_p.
__device__ __align__(16) unsigned int g_hist[4][RSIZE];

__device__ __forceinline__ unsigned int f2ord(float f) {
    unsigned int u = __float_as_uint(f);
    return (u & 0x80000000u) ? ~u : (u | 0x80000000u);
}

// -------------------------------------------------------------------------
// Kernel 1: channel max + argmax (first occurrence), emit u64 keys AND
// accumulate the pass-0 raw histogram into g_hist[0] (zero at entry;
// re-zeroed each replay by scatter pass 1). Channel axis split 4-ways
// across lanes; shfl_xor(1),(2) combine. grid = 4096 x 256.
// -------------------------------------------------------------------------
__global__ void compute_keys_kernel(const float* __restrict__ x) {
    __shared__ unsigned int h[256];
    h[threadIdx.x] = 0;
    __syncthreads();

    int gid   = blockIdx.x * 256 + threadIdx.x;   // 0 .. 1048575
    int chunk = gid & 3;                          // channel chunk (16 ch each)
    int qg    = gid >> 2;                         // global pixel-group
    int batch = qg >> 14;
    int q     = qg & 16383;

    const float4* xb = reinterpret_cast<const float4*>(x)
                       + (size_t)batch * (C_ * (HW_ / 4))
                       + (size_t)(chunk * 16) * (HW_ / 4) + q;

    float4 best = xb[0];
    int c0 = 0, c1 = 0, c2 = 0, c3 = 0;
    #pragma unroll
    for (int c = 1; c < 16; ++c) {
        float4 v = xb[(size_t)c * (HW_ / 4)];
        if (v.x > best.x) { best.x = v.x; c0 = c; }
        if (v.y > best.y) { best.y = v.y; c1 = c; }
        if (v.z > best.z) { best.z = v.z; c2 = c; }
        if (v.w > best.w) { best.w = v.w; c3 = c; }
    }
    int cb = chunk * 16;
    c0 += cb; c1 += cb; c2 += cb; c3 += cb;

    // Cross-chunk combine; equal value -> smaller channel = first occurrence.
    #pragma unroll
    for (int m = 1; m <= 2; m <<= 1) {
        float ox = __shfl_xor_sync(0xffffffffu, best.x, m);
        float oy = __shfl_xor_sync(0xffffffffu, best.y, m);
        float oz = __shfl_xor_sync(0xffffffffu, best.z, m);
        float ow = __shfl_xor_sync(0xffffffffu, best.w, m);
        int   o0 = __shfl_xor_sync(0xffffffffu, c0, m);
        int   o1 = __shfl_xor_sync(0xffffffffu, c1, m);
        int   o2 = __shfl_xor_sync(0xffffffffu, c2, m);
        int   o3 = __shfl_xor_sync(0xffffffffu, c3, m);
        if (ox > best.x || (ox == best.x && o0 < c0)) { best.x = ox; c0 = o0; }
        if (oy > best.y || (oy == best.y && o1 < c1)) { best.y = oy; c1 = o1; }
        if (oz > best.z || (oz == best.z && o2 < c2)) { best.z = oz; c2 = o2; }
        if (ow > best.w || (ow == best.w && o3 < c3)) { best.w = ow; c3 = o3; }
    }

    if (chunk == 0) {
        unsigned int e0 = f2ord(best.x), e1 = f2ord(best.y);
        unsigned int e2 = f2ord(best.z), e3 = f2ord(best.w);
        size_t o = (size_t)batch * HW_;
        unsigned int s = (unsigned int)q * 4u;
        ulonglong2 k01, k23;
        k01.x = ((unsigned long long)e0 << 32) | ((unsigned)c0 << 16) | (s + 0u);
        k01.y = ((unsigned long long)e1 << 32) | ((unsigned)c1 << 16) | (s + 1u);
        k23.x = ((unsigned long long)e2 << 32) | ((unsigned)c2 << 16) | (s + 2u);
        k23.y = ((unsigned long long)e3 << 32) | ((unsigned)c3 << 16) | (s + 3u);
        *reinterpret_cast<ulonglong2*>(g_kv0 + o + s)     = k01;
        *reinterpret_cast<ulonglong2*>(g_kv0 + o + s + 2) = k23;

        atomicAdd(&h[e0 & 255u], 1u);
        atomicAdd(&h[e1 & 255u], 1u);
        atomicAdd(&h[e2 & 255u], 1u);
        atomicAdd(&h[e3 & 255u], 1u);
    }
    __syncthreads();

    int local = (blockIdx.x & 255) >> 2;         // dest scatter block
    int batch_b = blockIdx.x >> 8;
    unsigned int cnt = h[threadIdx.x];
    if (cnt)
        atomicAdd(&g_hist[0][((size_t)batch_b * NBLK + local) * 256 + threadIdx.x], cnt);
}

// -------------------------------------------------------------------------
// Kernel 2: stable scatter with FUSED histogram scan (coalesced layout).
// Thread tid(=bin) reads its bin's 64 raw per-block counts (one 128B line
// per warp-load): bintot (batch bin total) and lpre (blocks < local).
// Block scan of bintot -> bin base. Streaming-ballot ranking; smem
// exchange for coalesced writes. RIN/ROUT/RZERO = hist region roles.
// grid = 1024 x 256.
// -------------------------------------------------------------------------
template <int SHIFT, int RIN, int ROUT, int RZERO, bool LAST>
__global__ void __launch_bounds__(THREADS, 4)
scatter_kernel(float4* __restrict__ outv) {
    __shared__ unsigned int       wh[NW][256];
    __shared__ unsigned long long s_kv[BSIZE];
    __shared__ unsigned int       dstart[256];
    __shared__ unsigned int       gbase[256];
    __shared__ unsigned int       sw[NW];
    __shared__ unsigned int       sw2[NW];

    const unsigned long long* __restrict__ in_kv  = (RIN & 1) ? g_kv1 : g_kv0;
    unsigned long long*       __restrict__ out_kv = (RIN & 1) ? g_kv0 : g_kv1;

    int tid = threadIdx.x;
    int w = tid >> 5, lane = tid & 31;
    unsigned int lt = (1u << lane) - 1u;
    for (int j = tid; j < NW * 256; j += THREADS)
        (&wh[0][0])[j] = 0;

    int blk = blockIdx.x, batch = blk >> 6, local = blk & 63;

    // Zero this block's slice of the rotation region (consumed last pass).
    g_hist[RZERO][(size_t)blk * 256 + tid] = 0u;
    __syncthreads();

    size_t base = (size_t)blk * BSIZE + (size_t)w * (32 * IPT);

    unsigned long long kv[IPT];
    unsigned int d[IPT];
    unsigned int rank[IPT];

    #pragma unroll
    for (int i = 0; i < IPT; ++i) {
        kv[i] = in_kv[base + i * 32 + lane];
        d[i] = (unsigned)(kv[i] >> (32 + SHIFT)) & 255u;
        rank[i] = 0;
    }

    // Streaming-ballot ranking (per-warp, stable).
    #pragma unroll
    for (int j = 0; j < IPT; ++j) {
        unsigned int bal[8];
        #pragma unroll
        for (int b = 0; b < 8; ++b)
            bal[b] = __ballot_sync(0xffffffffu, (d[j] >> b) & 1u);
        #pragma unroll
        for (int i = j; i < IPT; ++i) {
            unsigned int m = 0xffffffffu;
            #pragma unroll
            for (int b = 0; b < 8; ++b)
                m &= bal[b] ^ (((d[i] >> b) & 1u) - 1u);
            if (i == j) {
                unsigned int rw = __popc(m & lt);
                rank[i] += rw;
                if (rw == 0)
                    atomicAdd(&wh[w][d[i]], __popc(m));
            } else {
                rank[i] += __popc(m);
            }
        }
    }

    // Fused hist scan (coalesced): for each local block j, one 128B line
    // per warp. bintot = batch total of bin tid; lpre = blocks before ours.
    const unsigned int* hb = g_hist[RIN] + (size_t)batch * (NBLK * 256) + tid;
    unsigned int lpre = 0, bintot = 0;
    #pragma unroll
    for (int j = 0; j < NBLK; ++j) {
        unsigned int hv = hb[j * 256];
        bintot += hv;
        if (j < local) lpre += hv;
    }
    __syncthreads();

    // Per-bin cross-warp scan of own-block counts (bin = tid).
    unsigned int running = 0;
    #pragma unroll
    for (int q = 0; q < NW; ++q) {
        unsigned int t = wh[q][tid];
        wh[q][tid] = running;
        running += t;
    }

    // Two block-wide exclusive scans (own counts -> dstart; bintot -> base).
    unsigned int inc1 = running, inc2 = bintot;
    #pragma unroll
    for (int o = 1; o < 32; o <<= 1) {
        unsigned int t1 = __shfl_up_sync(0xffffffffu, inc1, o);
        unsigned int t2 = __shfl_up_sync(0xffffffffu, inc2, o);
        if (lane >= o) { inc1 += t1; inc2 += t2; }
    }
    if (lane == 31) { sw[w] = inc1; sw2[w] = inc2; }
    __syncthreads();
    if (tid == 0) {
        unsigned int r1 = 0, r2 = 0;
        #pragma unroll
        for (int q = 0; q < NW; ++q) {
            unsigned int t1 = sw[q];  sw[q]  = r1; r1 += t1;
            unsigned int t2 = sw2[q]; sw2[q] = r2; r2 += t2;
        }
    }
    __syncthreads();
    unsigned int excl    = inc1 - running + sw[w];    // in-block digit start
    unsigned int binBase = inc2 - bintot  + sw2[w];   // batch-global bin start
    dstart[tid] = excl;
    gbase[tid]  = binBase + lpre - excl;
    __syncthreads();

    // Exchange into block-digit-sorted order.
    #pragma unroll
    for (int i = 0; i < IPT; ++i) {
        unsigned int p = dstart[d[i]] + wh[w][d[i]] + rank[i];
        s_kv[p] = kv[i];
    }
    __syncthreads();

    // Coalesced write-out; global pos = gbase[digit] + p.
    size_t obase = (size_t)batch * HW_;
    #pragma unroll
    for (int j = 0; j < IPT; ++j) {
        unsigned int p = (unsigned int)tid + j * THREADS;
        unsigned long long k = s_kv[p];
        unsigned int dd = (unsigned)(k >> (32 + SHIFT)) & 255u;
        unsigned int pos = gbase[dd] + p;
        if (!LAST) {
            out_kv[obase + pos] = k;
            unsigned int d2 = (unsigned)(k >> (40 + SHIFT)) & 255u;
            atomicAdd(&g_hist[ROUT][((size_t)batch * NBLK + (pos >> 10)) * 256 + d2], 1u);
        } else {
            unsigned int hi = (unsigned int)(k >> 32);
            unsigned int u  = (hi & 0x80000000u) ? (hi ^ 0x80000000u) : ~hi;
            unsigned int lo = (unsigned int)k & 0x3FFFFFu;   // c<<16 | s == flat idx
            unsigned int s  = lo & 0xFFFFu;
            float4 o;
            o.x = __uint_as_float(u);
            o.y = (float)lo;                      // c*65536 + s, < 2^22, exact
            o.z = (float)(s >> 8);                // row (W=256)
            o.w = (float)(s & 255u);              // col
            outv[obase + pos] = o;
        }
    }
}

// -------------------------------------------------------------------------
// Region rotation (verified across graph replays; globals start zeroed):
//   R0: ck produces, s0 reads, s1 zeroes.
//   R1: s0 produces, s1 reads, s2 zeroes.
//   R2: s1 produces, s2 reads, s3 zeroes.
//   R3: s2 produces, s3 reads, s0 zeroes (before s2 of the same replay).
// -------------------------------------------------------------------------
extern "C" void kernel_launch(void* const* d_in, const int* in_sizes, int n_in,
                              void* d_out, int out_size) {
    const float* x = (const float*)d_in[0];
    float4* out = (float4*)d_out;

    compute_keys_kernel<<<4096, 256>>>(x);                        // keys + hist -> R0
    scatter_kernel< 0, 0, 1, 3, false><<<GRID, THREADS>>>(nullptr); // kv0->kv1
    scatter_kernel< 8, 1, 2, 0, false><<<GRID, THREADS>>>(nullptr); // kv1->kv0
    scatter_kernel<16, 2, 3, 1, false><<<GRID, THREADS>>>(nullptr); // kv0->kv1
    scatter_kernel<24, 3, 0, 2, true ><<<GRID, THREADS>>>(out);     // kv1->d_out
}

// round 13
// speedup vs baseline: 1.5449x; 1.1318x over previous
#include <cuda_runtime.h>
#include <cstdint>

// Problem constants
#define B_      16
#define C_      64
#define HW_     65536      // 256*256

// Radix sort: 4 stable LSD passes of 8 bits over the 32-bit ordered-float
// value (high half of a u64 key). Low bits: channel<<16 | spatial(16).
// Keys generated in spatial order; stability => jnp argsort tie order.
#define THREADS 256
#define NW      8
#define IPT     4
#define BSIZE   1024               // THREADS * IPT
#define NBLK    64                 // HW_ / BSIZE
#define GRID    (B_ * NBLK)        // 1024 scatter blocks
#define RSIZE   (B_ * NBLK * 256)  // 262144 entries per hist region

__device__ __align__(16) unsigned long long g_kv0[B_ * HW_];
__device__ __align__(16) unsigned long long g_kv1[B_ * HW_];
// 4 rotating RAW histogram regions, layout (batch, local_block, bin) --
// bin fastest so fused-scan reads are coalesced (1 line per warp-load).
// Producers: compute_keys->R0, s0->R1, s1->R2, s2->R3. Readers: s_p -> R_p.
// Zero-rotation: s0 zeroes R3, s1->R0, s2->R1, s3->R2.
__device__ __align__(16) unsigned int g_hist[4][RSIZE];

__device__ __forceinline__ unsigned int f2ord(float f) {
    unsigned int u = __float_as_uint(f);
    return (u & 0x80000000u) ? ~u : (u | 0x80000000u);
}

// -------------------------------------------------------------------------
// Kernel 1: channel max + argmax (first occurrence), emit u64 keys AND
// accumulate the pass-0 raw histogram into g_hist[0]. Channel axis split
// 4-ways across lanes; shfl_xor(1),(2) combine. grid = 4096 x 256.
// -------------------------------------------------------------------------
__global__ void compute_keys_kernel(const float* __restrict__ x) {
    __shared__ unsigned int h[256];
    h[threadIdx.x] = 0;
    __syncthreads();

    int gid   = blockIdx.x * 256 + threadIdx.x;   // 0 .. 1048575
    int chunk = gid & 3;                          // channel chunk (16 ch each)
    int qg    = gid >> 2;                         // global pixel-group
    int batch = qg >> 14;
    int q     = qg & 16383;

    const float4* xb = reinterpret_cast<const float4*>(x)
                       + (size_t)batch * (C_ * (HW_ / 4))
                       + (size_t)(chunk * 16) * (HW_ / 4) + q;

    float4 best = xb[0];
    int c0 = 0, c1 = 0, c2 = 0, c3 = 0;
    #pragma unroll
    for (int c = 1; c < 16; ++c) {
        float4 v = xb[(size_t)c * (HW_ / 4)];
        if (v.x > best.x) { best.x = v.x; c0 = c; }
        if (v.y > best.y) { best.y = v.y; c1 = c; }
        if (v.z > best.z) { best.z = v.z; c2 = c; }
        if (v.w > best.w) { best.w = v.w; c3 = c; }
    }
    int cb = chunk * 16;
    c0 += cb; c1 += cb; c2 += cb; c3 += cb;

    // Cross-chunk combine; equal value -> smaller channel = first occurrence.
    #pragma unroll
    for (int m = 1; m <= 2; m <<= 1) {
        float ox = __shfl_xor_sync(0xffffffffu, best.x, m);
        float oy = __shfl_xor_sync(0xffffffffu, best.y, m);
        float oz = __shfl_xor_sync(0xffffffffu, best.z, m);
        float ow = __shfl_xor_sync(0xffffffffu, best.w, m);
        int   o0 = __shfl_xor_sync(0xffffffffu, c0, m);
        int   o1 = __shfl_xor_sync(0xffffffffu, c1, m);
        int   o2 = __shfl_xor_sync(0xffffffffu, c2, m);
        int   o3 = __shfl_xor_sync(0xffffffffu, c3, m);
        if (ox > best.x || (ox == best.x && o0 < c0)) { best.x = ox; c0 = o0; }
        if (oy > best.y || (oy == best.y && o1 < c1)) { best.y = oy; c1 = o1; }
        if (oz > best.z || (oz == best.z && o2 < c2)) { best.z = oz; c2 = o2; }
        if (ow > best.w || (ow == best.w && o3 < c3)) { best.w = ow; c3 = o3; }
    }

    if (chunk == 0) {
        unsigned int e0 = f2ord(best.x), e1 = f2ord(best.y);
        unsigned int e2 = f2ord(best.z), e3 = f2ord(best.w);
        size_t o = (size_t)batch * HW_;
        unsigned int s = (unsigned int)q * 4u;
        ulonglong2 k01, k23;
        k01.x = ((unsigned long long)e0 << 32) | ((unsigned)c0 << 16) | (s + 0u);
        k01.y = ((unsigned long long)e1 << 32) | ((unsigned)c1 << 16) | (s + 1u);
        k23.x = ((unsigned long long)e2 << 32) | ((unsigned)c2 << 16) | (s + 2u);
        k23.y = ((unsigned long long)e3 << 32) | ((unsigned)c3 << 16) | (s + 3u);
        *reinterpret_cast<ulonglong2*>(g_kv0 + o + s)     = k01;
        *reinterpret_cast<ulonglong2*>(g_kv0 + o + s + 2) = k23;

        atomicAdd(&h[e0 & 255u], 1u);
        atomicAdd(&h[e1 & 255u], 1u);
        atomicAdd(&h[e2 & 255u], 1u);
        atomicAdd(&h[e3 & 255u], 1u);
    }
    __syncthreads();

    int local = (blockIdx.x & 255) >> 2;         // dest scatter block
    int batch_b = blockIdx.x >> 8;
    unsigned int cnt = h[threadIdx.x];
    if (cnt)
        atomicAdd(&g_hist[0][((size_t)batch_b * NBLK + local) * 256 + threadIdx.x], cnt);
}

// -------------------------------------------------------------------------
// Kernel 2: stable scatter with fused (coalesced) histogram scan.
// Phase order: issue kv loads -> hist-scan loop (L2 latency overlaps
// ranking) -> streaming-ballot ranking -> scans -> exchange -> write.
// grid = 1024 x 256.
// -------------------------------------------------------------------------
template <int SHIFT, int RIN, int ROUT, int RZERO, bool LAST>
__global__ void __launch_bounds__(THREADS, 6)
scatter_kernel(float4* __restrict__ outv) {
    __shared__ unsigned int       wh[NW][256];
    __shared__ unsigned long long s_kv[BSIZE];
    __shared__ unsigned int       dstart[256];
    __shared__ unsigned int       gbase[256];
    __shared__ unsigned int       sw[NW];
    __shared__ unsigned int       sw2[NW];

    const unsigned long long* __restrict__ in_kv  = (RIN & 1) ? g_kv1 : g_kv0;
    unsigned long long*       __restrict__ out_kv = (RIN & 1) ? g_kv0 : g_kv1;

    int tid = threadIdx.x;
    int w = tid >> 5, lane = tid & 31;
    unsigned int lt = (1u << lane) - 1u;
    for (int j = tid; j < NW * 256; j += THREADS)
        (&wh[0][0])[j] = 0;

    int blk = blockIdx.x, batch = blk >> 6, local = blk & 63;

    // Zero this block's slice of the rotation region (consumed last pass).
    g_hist[RZERO][(size_t)blk * 256 + tid] = 0u;
    __syncthreads();

    size_t base = (size_t)blk * BSIZE + (size_t)w * (32 * IPT);

    unsigned long long kv[IPT];
    unsigned int d[IPT];
    unsigned int rank[IPT];

    // Issue kv loads first.
    #pragma unroll
    for (int i = 0; i < IPT; ++i)
        kv[i] = in_kv[base + i * 32 + lane];

    // Fused hist scan (coalesced; partial unroll caps the reg window).
    // bintot = batch total of bin tid; lpre = count in blocks < local.
    const unsigned int* hb = g_hist[RIN] + (size_t)batch * (NBLK * 256) + tid;
    unsigned int lpre = 0, bintot = 0;
    #pragma unroll 8
    for (int j = 0; j < NBLK; ++j) {
        unsigned int hv = hb[j * 256];
        bintot += hv;
        if (j < local) lpre += hv;
    }

    #pragma unroll
    for (int i = 0; i < IPT; ++i) {
        d[i] = (unsigned)(kv[i] >> (32 + SHIFT)) & 255u;
        rank[i] = 0;
    }

    // Streaming-ballot ranking (per-warp, stable).
    #pragma unroll
    for (int j = 0; j < IPT; ++j) {
        unsigned int bal[8];
        #pragma unroll
        for (int b = 0; b < 8; ++b)
            bal[b] = __ballot_sync(0xffffffffu, (d[j] >> b) & 1u);
        #pragma unroll
        for (int i = j; i < IPT; ++i) {
            unsigned int m = 0xffffffffu;
            #pragma unroll
            for (int b = 0; b < 8; ++b)
                m &= bal[b] ^ (((d[i] >> b) & 1u) - 1u);
            if (i == j) {
                unsigned int rw = __popc(m & lt);
                rank[i] += rw;
                if (rw == 0)
                    atomicAdd(&wh[w][d[i]], __popc(m));
            } else {
                rank[i] += __popc(m);
            }
        }
    }
    __syncthreads();

    // Per-bin cross-warp scan of own-block counts (bin = tid).
    unsigned int running = 0;
    #pragma unroll
    for (int q = 0; q < NW; ++q) {
        unsigned int t = wh[q][tid];
        wh[q][tid] = running;
        running += t;
    }

    // Two block-wide exclusive scans (own counts -> dstart; bintot -> base).
    unsigned int inc1 = running, inc2 = bintot;
    #pragma unroll
    for (int o = 1; o < 32; o <<= 1) {
        unsigned int t1 = __shfl_up_sync(0xffffffffu, inc1, o);
        unsigned int t2 = __shfl_up_sync(0xffffffffu, inc2, o);
        if (lane >= o) { inc1 += t1; inc2 += t2; }
    }
    if (lane == 31) { sw[w] = inc1; sw2[w] = inc2; }
    __syncthreads();
    if (tid == 0) {
        unsigned int r1 = 0, r2 = 0;
        #pragma unroll
        for (int q = 0; q < NW; ++q) {
            unsigned int t1 = sw[q];  sw[q]  = r1; r1 += t1;
            unsigned int t2 = sw2[q]; sw2[q] = r2; r2 += t2;
        }
    }
    __syncthreads();
    unsigned int excl    = inc1 - running + sw[w];    // in-block digit start
    unsigned int binBase = inc2 - bintot  + sw2[w];   // batch-global bin start
    dstart[tid] = excl;
    gbase[tid]  = binBase + lpre - excl;
    __syncthreads();

    // Exchange into block-digit-sorted order.
    #pragma unroll
    for (int i = 0; i < IPT; ++i) {
        unsigned int p = dstart[d[i]] + wh[w][d[i]] + rank[i];
        s_kv[p] = kv[i];
    }
    __syncthreads();

    // Coalesced write-out; global pos = gbase[digit] + p.
    size_t obase = (size_t)batch * HW_;
    #pragma unroll
    for (int j = 0; j < IPT; ++j) {
        unsigned int p = (unsigned int)tid + j * THREADS;
        unsigned long long k = s_kv[p];
        unsigned int dd = (unsigned)(k >> (32 + SHIFT)) & 255u;
        unsigned int pos = gbase[dd] + p;
        if (!LAST) {
            out_kv[obase + pos] = k;
            unsigned int d2 = (unsigned)(k >> (40 + SHIFT)) & 255u;
            atomicAdd(&g_hist[ROUT][((size_t)batch * NBLK + (pos >> 10)) * 256 + d2], 1u);
        } else {
            unsigned int hi = (unsigned int)(k >> 32);
            unsigned int u  = (hi & 0x80000000u) ? (hi ^ 0x80000000u) : ~hi;
            unsigned int lo = (unsigned int)k & 0x3FFFFFu;   // c<<16 | s == flat idx
            unsigned int s  = lo & 0xFFFFu;
            float4 o;
            o.x = __uint_as_float(u);
            o.y = (float)lo;                      // c*65536 + s, < 2^22, exact
            o.z = (float)(s >> 8);                // row (W=256)
            o.w = (float)(s & 255u);              // col
            outv[obase + pos] = o;
        }
    }
}

// -------------------------------------------------------------------------
// Region rotation (verified across graph replays; globals start zeroed):
//   R0: ck produces, s0 reads, s1 zeroes.
//   R1: s0 produces, s1 reads, s2 zeroes.
//   R2: s1 produces, s2 reads, s3 zeroes.
//   R3: s2 produces, s3 reads, s0 zeroes (before s2 of the same replay).
// -------------------------------------------------------------------------
extern "C" void kernel_launch(void* const* d_in, const int* in_sizes, int n_in,
                              void* d_out, int out_size) {
    const float* x = (const float*)d_in[0];
    float4* out = (float4*)d_out;

    compute_keys_kernel<<<4096, 256>>>(x);                        // keys + hist -> R0
    scatter_kernel< 0, 0, 1, 3, false><<<GRID, THREADS>>>(nullptr); // kv0->kv1
    scatter_kernel< 8, 1, 2, 0, false><<<GRID, THREADS>>>(nullptr); // kv1->kv0
    scatter_kernel<16, 2, 3, 1, false><<<GRID, THREADS>>>(nullptr); // kv0->kv1
    scatter_kernel<24, 3, 0, 2, true ><<<GRID, THREADS>>>(out);     // kv1->d_out
}